// round 9
// baseline (speedup 1.0000x reference)
#include <cuda_runtime.h>
#include <cuda_fp16.h>
#include <math.h>

#define BB 32
#define HH 1024
#define WW 1024
#define RAD 15            // kernel 31, radius 15
#define INV_K2 (1.0f/961.0f)
#define SMOOTH 0.001f

#define TW 128                         // output tile width
#define TH 128                         // output tile height
#define STRIP 160                      // TW + 2*16 halo columns
#define TOTBLK ((WW/TW)*(HH/TH)*BB)    // 8*8*32 = 2048

__device__ float g_inter[BB];
__device__ float g_mask[BB];
__device__ int   g_done = 0;

// ---------------------------------------------------------------------------
// Single fused kernel.
// Phase 1: threads 0..159 compute the vertical 31-row box sum of target for
//   one strip column each (tile cols x0-16 .. x0+143), sliding down TH rows;
//   results stored fp16 in smem. Out-of-image columns store zeros, so
//   phase 2 needs NO bounds checks at all.
// Phase 2: horizontal 31-col sliding sum from smem (register-folded window:
//   middles folded into the init sum, only 7+7 edge values stay live), fused
//   with sigmoid/weight/Dice partials. Thread t: col-group g = t&15
//   (8 cols), row-lane rl = t>>4, 8 passes of 16 rows.
// Last block (done-counter) computes the scalar loss and RESETS the
// accumulators so graph replays start clean.
// ---------------------------------------------------------------------------
__global__ __launch_bounds__(256, 5)
void k_fused(const float* __restrict__ output,
             const float* __restrict__ target,
             float* __restrict__ lossOut) {
    __shared__ __half vsum[TH][STRIP];      // 40 KB; row stride 320 B (16B-mult)
    __shared__ float red_i[8], red_m[8];
    __shared__ bool  isLast;

    const int tid = threadIdx.x;
    const int b   = blockIdx.z;
    const int x0  = blockIdx.x * TW;
    const int y0  = blockIdx.y * TH;

    const float* __restrict__ tg = target + (size_t)b * HH * WW;
    const float* __restrict__ op = output + (size_t)b * HH * WW;

    // ================= phase 1: vertical sums -> smem =================
    if (tid < STRIP) {
        const int c = x0 - 16 + tid;                 // global column
        if (c >= 0 && c < WW) {
            const float* __restrict__ col = tg + c;
            float s = 0.f;
            // preload rows [y0-15, y0+14] (top guard only; y0+14 <= 910 < HH)
            #pragma unroll 5
            for (int r = y0 - RAD; r < y0 + RAD; r++)
                if (r >= 0) s += col[(size_t)r * WW];
            // peeled first output (y = y0): add row y0+15 (always < HH)
            s += col[(size_t)(y0 + RAD) * WW];
            vsum[0][tid] = __float2half_rn(s);
            #pragma unroll 4
            for (int y = y0 + 1; y < y0 + TH; y++) {
                const int ra = y + RAD;
                if (ra < HH) s += col[(size_t)ra * WW];
                const int rs = y - RAD - 1;          // added 31 iters ago: L1/L2 hit
                if (rs >= 0) s -= col[(size_t)rs * WW];
                vsum[y - y0][tid] = __float2half_rn(s);
            }
        } else {
            // out-of-image columns: zero so phase 2 is branch-free
            for (int yl = 0; yl < TH; yl++)
                vsum[yl][tid] = __float2half_rn(0.f);
        }
    }
    __syncthreads();

    // ================= phase 2: horizontal window + loss =================
    const int g  = tid & 15;            // col-group: tile cols [8g, 8g+8)
    const int rl = tid >> 4;            // row lane 0..15
    float li = 0.0f, lm = 0.0f;

    #pragma unroll
    for (int pass = 0; pass < 8; pass++) {
        const int r = pass * 16 + rl;                // tile row 0..127
        const int y = y0 + r;
        // smem window: global cols x0+8g-16 .. x0+8g+23 -> smem cols 8g..8g+39
        const uint4* __restrict__ v4 = (const uint4*)vsum[r];   // 8 halves per uint4

        float s = 0.0f;
        float lo0,lo1,lo2,lo3,lo4,lo5,lo6;           // v[1..7]  (outgoing)
        float hi0,hi1,hi2,hi3,hi4,hi5,hi6;           // v[32..38] (incoming)

        {   // chunk 0: v[0..7] -> keep v[1..7], fold them into s
            uint4 u = v4[g];
            float2 a = __half22float2(*(const __half2*)&u.x);
            float2 bq = __half22float2(*(const __half2*)&u.y);
            float2 c = __half22float2(*(const __half2*)&u.z);
            float2 d = __half22float2(*(const __half2*)&u.w);
            lo0=a.y; lo1=bq.x; lo2=bq.y; lo3=c.x; lo4=c.y; lo5=d.x; lo6=d.y;
            s += a.y+bq.x+bq.y+c.x+c.y+d.x+d.y;
        }
        #pragma unroll
        for (int j = 1; j <= 3; j++) {               // chunks 1..3: fold v[8..31]
            uint4 u = v4[g + j];
            float2 a = __half22float2(*(const __half2*)&u.x);
            float2 bq = __half22float2(*(const __half2*)&u.y);
            float2 c = __half22float2(*(const __half2*)&u.z);
            float2 d = __half22float2(*(const __half2*)&u.w);
            s += a.x+a.y+bq.x+bq.y+c.x+c.y+d.x+d.y;
        }
        {   // chunk 4: v[32..39] -> keep v[32..38]
            uint4 u = v4[g + 4];
            float2 a = __half22float2(*(const __half2*)&u.x);
            float2 bq = __half22float2(*(const __half2*)&u.y);
            float2 c = __half22float2(*(const __half2*)&u.z);
            float2 d = __half22float2(*(const __half2*)&u.w);
            hi0=a.x; hi1=a.y; hi2=bq.x; hi3=bq.y; hi4=c.x; hi5=c.y; hi6=d.x;
        }

        // target / output for cols x0+8g..x0+8g+7 (target likely L2-hot from phase 1)
        const float4* __restrict__ trow = (const float4*)(tg + (size_t)y * WW + x0);
        const float4* __restrict__ orow = (const float4*)(op + (size_t)y * WW + x0);
        float4 ta = trow[2*g],       tb = trow[2*g + 1];
        float4 oa = __ldcs(&orow[2*g]), ob = __ldcs(&orow[2*g + 1]);
        float tv[8] = {ta.x, ta.y, ta.z, ta.w, tb.x, tb.y, tb.z, tb.w};
        float ov[8] = {oa.x, oa.y, oa.z, oa.w, ob.x, ob.y, ob.z, ob.w};
        float inc[7]  = {hi0, hi1, hi2, hi3, hi4, hi5, hi6};
        float outv[7] = {lo0, lo1, lo2, lo3, lo4, lo5, lo6};

        #pragma unroll
        for (int k = 0; k < 8; k++) {
            if (k) s += inc[k-1] - outv[k-1];        // slide window
            const float avg = s * INV_K2;
            const float w   = 1.0f + 5.0f * fabsf(avg - tv[k]);
            const float sig = __fdividef(1.0f, 1.0f + __expf(-ov[k]));
            li += sig * tv[k] * w;
            lm += (tv[k] + sig) * w;
        }
    }

    // ================= reduction + finalize =================
    #pragma unroll
    for (int off = 16; off > 0; off >>= 1) {
        li += __shfl_down_sync(0xFFFFFFFFu, li, off);
        lm += __shfl_down_sync(0xFFFFFFFFu, lm, off);
    }
    const int warp = tid >> 5, lane = tid & 31;
    if (lane == 0) { red_i[warp] = li; red_m[warp] = lm; }
    __syncthreads();
    if (tid == 0) {
        float si = 0.f, sm = 0.f;
        #pragma unroll
        for (int w = 0; w < 8; w++) { si += red_i[w]; sm += red_m[w]; }
        atomicAdd(&g_inter[b], si);
        atomicAdd(&g_mask[b], sm);
        __threadfence();
        int c = atomicAdd(&g_done, 1);
        isLast = (c == TOTBLK - 1);
    }
    __syncthreads();

    if (isLast && tid == 0) {
        __threadfence();
        float l = 0.0f;
        #pragma unroll
        for (int k = 0; k < BB; k++)
            l += 1.0f - (2.0f * g_inter[k] + SMOOTH) / (g_mask[k] + SMOOTH);
        lossOut[0] = l * (1.0f / (float)BB);
        // reset ALL persistent state for the next graph replay
        #pragma unroll
        for (int k = 0; k < BB; k++) { g_inter[k] = 0.0f; g_mask[k] = 0.0f; }
        g_done = 0;
    }
}

// ---------------------------------------------------------------------------
extern "C" void kernel_launch(void* const* d_in, const int* in_sizes, int n_in,
                              void* d_out, int out_size) {
    const float* output = (const float*)d_in[0];   // metadata order: output, target
    const float* target = (const float*)d_in[1];
    float* out = (float*)d_out;

    dim3 grid(WW / TW, HH / TH, BB);               // (8, 8, 32)
    k_fused<<<grid, 256>>>(output, target, out);
}